// round 1
// baseline (speedup 1.0000x reference)
#include <cuda_runtime.h>
#include <cuda_bf16.h>
#include <math.h>

// ----------------------------------------------------------------------------
// TernaryConv2d: out = conv2d(x, ternarize(w), pad=1) + bias
// x: [16,64,224,224] f32, w: [64,64,3,3] f32, bias: [64] f32
// ----------------------------------------------------------------------------

#define N_BATCH 16
#define C_IN    64
#define C_OUT   64
#define HW      224
#define KSIZE   9            // 3x3
#define FILT    (C_IN * KSIZE)   // 576 elements per output filter

// Scratch for ternarized weights (no cudaMalloc allowed)
__device__ float g_tw[C_OUT * FILT];

// ---------------------------------------------------------------------------
// f32x2 packed helpers (Blackwell sm_103a packed fp32 pipe)
// ---------------------------------------------------------------------------
__device__ __forceinline__ unsigned long long ffma2(unsigned long long a,
                                                    unsigned long long b,
                                                    unsigned long long c) {
    unsigned long long d;
    asm("fma.rn.f32x2 %0, %1, %2, %3;" : "=l"(d) : "l"(a), "l"(b), "l"(c));
    return d;
}
__device__ __forceinline__ unsigned long long pack2(float lo, float hi) {
    unsigned long long d;
    asm("mov.b64 %0, {%1, %2};" : "=l"(d) : "f"(lo), "f"(hi));
    return d;
}
__device__ __forceinline__ float2 unpack2(unsigned long long v) {
    float2 r;
    asm("mov.b64 {%0, %1}, %2;" : "=f"(r.x), "=f"(r.y) : "l"(v));
    return r;
}

// ---------------------------------------------------------------------------
// Kernel 1: ternarize weights (TWN), fold alpha. One block per output channel.
// delta = 0.7/576 * sum|w|; alpha = mean(|w| over |w|>delta), clamped >= 1e-4
// tw = sign_pattern * alpha
// ---------------------------------------------------------------------------
__global__ void ternarize_kernel(const float* __restrict__ w) {
    const int co = blockIdx.x;
    const float* wp = w + co * FILT;
    const int tid = threadIdx.x;   // 256 threads

    __shared__ float redf[256];
    __shared__ int   redi[256];

    // pass 1: sum |w|
    float s = 0.0f;
    for (int i = tid; i < FILT; i += 256) s += fabsf(wp[i]);
    redf[tid] = s;
    __syncthreads();
    for (int st = 128; st > 0; st >>= 1) {
        if (tid < st) redf[tid] += redf[tid + st];
        __syncthreads();
    }
    const float delta = (0.7f / (float)FILT) * redf[0];
    __syncthreads();

    // pass 2: count & masked sum
    float ms = 0.0f; int cnt = 0;
    for (int i = tid; i < FILT; i += 256) {
        float a = fabsf(wp[i]);
        if (a > delta) { ms += a; cnt++; }
    }
    redf[tid] = ms; redi[tid] = cnt;
    __syncthreads();
    for (int st = 128; st > 0; st >>= 1) {
        if (tid < st) { redf[tid] += redf[tid + st]; redi[tid] += redi[tid + st]; }
        __syncthreads();
    }
    int count = redi[0];
    if (count == 0) count = 1;
    float alpha = redf[0] / (float)count;
    alpha = fmaxf(alpha, 1e-4f);

    // pass 3: write tern * alpha
    for (int i = tid; i < FILT; i += 256) {
        float v = wp[i];
        float t = (v > delta) ? 1.0f : ((v < -delta) ? -1.0f : 0.0f);
        g_tw[co * FILT + i] = t * alpha;
    }
}

// ---------------------------------------------------------------------------
// Kernel 2: direct 3x3 conv, fp32 with packed f32x2 math.
// Block: 32x32 spatial tile x 4 output channels, one image n.
//   threads: 256 = tx(8 col-quads) x ty(8 row-quads) x tz(4 co)
//   per thread: 4 rows x 4 cols (2 f32x2 pairs per row) of one co.
// Input tile (34x34) staged in smem per ci (reused across 4 co);
// all block weights (4co x 64ci x 9) staged in smem once.
// ---------------------------------------------------------------------------
#define TILE 32
#define CO_B 4
#define SX_STRIDE 36   // 34 cols padded; keeps float4 rows 16B aligned

__global__ __launch_bounds__(256, 4)
void conv_kernel(const float* __restrict__ x,
                 const float* __restrict__ bias,
                 float* __restrict__ out) {
    __shared__ float sx[34 * SX_STRIDE];
    __shared__ float sw[CO_B * C_IN * KSIZE];   // [tz][ci][k]

    const int tid = threadIdx.x;
    const int tx = tid & 7;          // column quad (4 cols each)
    const int ty = (tid >> 3) & 7;   // row quad (4 rows each)
    const int tz = tid >> 6;         // local co
    const int wt = blockIdx.x;       // 0..6
    const int ht = blockIdx.y;       // 0..6
    const int n   = blockIdx.z >> 4;
    const int cog = blockIdx.z & 15;
    const int w0 = wt * TILE;
    const int h0 = ht * TILE;

    // Stage this block's weights: contiguous slice of g_tw
    for (int i = tid; i < CO_B * C_IN * KSIZE; i += 256)
        sw[i] = g_tw[cog * CO_B * FILT + i];

    unsigned long long acc[4][2];
#pragma unroll
    for (int r = 0; r < 4; r++) { acc[r][0] = 0ull; acc[r][1] = 0ull; }

    const float* xn = x + (size_t)n * C_IN * HW * HW;

    for (int ci = 0; ci < C_IN; ci++) {
        __syncthreads();   // previous iter done reading sx (also covers sw on iter 0)
        // ---- stage input tile (34x34, halo=1, zero-padded edges) ----
        const float* xc = xn + ci * HW * HW;
        for (int i = tid; i < 34 * 34; i += 256) {
            int r = i / 34, c = i - r * 34;
            int gh = h0 + r - 1;
            int gw = w0 + c - 1;
            float v = 0.0f;
            if ((unsigned)gh < (unsigned)HW && (unsigned)gw < (unsigned)HW)
                v = xc[gh * HW + gw];
            sx[r * SX_STRIDE + c] = v;
        }
        __syncthreads();

        // duplicate weights into f32x2 pairs once per ci
        unsigned long long wp[9];
#pragma unroll
        for (int k = 0; k < 9; k++) {
            float wv = sw[(tz * C_IN + ci) * KSIZE + k];
            wp[k] = pack2(wv, wv);
        }

        // 6 input rows cover 4 output rows (kh = ir - r)
#pragma unroll
        for (int ir = 0; ir < 6; ir++) {
            const float* row = &sx[(ty * 4 + ir) * SX_STRIDE + tx * 4];
            float4 v4 = *(const float4*)row;         // cols 0..3
            float2 v2 = *(const float2*)(row + 4);   // cols 4..5
            unsigned long long E0 = pack2(v4.x, v4.y);  // (x0,x1)
            unsigned long long E1 = pack2(v4.z, v4.w);  // (x2,x3)
            unsigned long long E2 = pack2(v2.x, v2.y);  // (x4,x5)
            unsigned long long O0 = pack2(v4.y, v4.z);  // (x1,x2)
            unsigned long long O1 = pack2(v4.w, v2.x);  // (x3,x4)
#pragma unroll
            for (int r = 0; r < 4; r++) {
                const int kh = ir - r;
                if (kh >= 0 && kh < 3) {
                    acc[r][0] = ffma2(E0, wp[kh * 3 + 0], acc[r][0]);
                    acc[r][1] = ffma2(E1, wp[kh * 3 + 0], acc[r][1]);
                    acc[r][0] = ffma2(O0, wp[kh * 3 + 1], acc[r][0]);
                    acc[r][1] = ffma2(O1, wp[kh * 3 + 1], acc[r][1]);
                    acc[r][0] = ffma2(E1, wp[kh * 3 + 2], acc[r][0]);
                    acc[r][1] = ffma2(E2, wp[kh * 3 + 2], acc[r][1]);
                }
            }
        }
    }

    // ---- epilogue: + bias, vectorized store ----
    const int co = cog * CO_B + tz;
    const float b = __ldg(&bias[co]);
    float* op = out + (((size_t)n * C_OUT + co) * HW + (h0 + ty * 4)) * HW
                    + w0 + tx * 4;
#pragma unroll
    for (int r = 0; r < 4; r++) {
        float2 a0 = unpack2(acc[r][0]);
        float2 a1 = unpack2(acc[r][1]);
        float4 o;
        o.x = a0.x + b; o.y = a0.y + b; o.z = a1.x + b; o.w = a1.y + b;
        *(float4*)(op + r * HW) = o;
    }
}

// ---------------------------------------------------------------------------
extern "C" void kernel_launch(void* const* d_in, const int* in_sizes, int n_in,
                              void* d_out, int out_size) {
    const float* x      = (const float*)d_in[0];
    const float* weight = (const float*)d_in[1];
    const float* bias   = (const float*)d_in[2];
    float* out = (float*)d_out;

    ternarize_kernel<<<C_OUT, 256>>>(weight);

    dim3 grid(HW / TILE, HW / TILE, N_BATCH * (C_OUT / CO_B));  // 7,7,256
    conv_kernel<<<grid, 256>>>(x, bias, out);
}

// round 3
// speedup vs baseline: 3.6456x; 3.6456x over previous
#include <cuda_runtime.h>
#include <cuda_bf16.h>
#include <math.h>
#include <stdint.h>

// ----------------------------------------------------------------------------
// TernaryConv2d: out = conv2d(x, ternarize(w), pad=1) + bias
// x: [16,64,224,224] f32, w: [64,64,3,3] f32, bias: [64] f32
// Strategy: tf32 tensor-core implicit GEMM. Weights enter the MMA as exact
// {-1,0,+1} (tf32-exact); per-channel alpha folded into the epilogue.
// ----------------------------------------------------------------------------

#define N_BATCH 16
#define C_IN    64
#define C_OUT   64
#define HW      224
#define FILT    (C_IN * 9)     // 576
#define WTILE   112            // output width per block (2 tiles per row)

// Reorganized ternary weights: [cich(8)][khw(9)][co(64)][slot(8)]
// slot = 2*(cii&3) + (cii>>2)  (k-interleave so (k, k+4) are an LDS.64 pair)
__device__ float g_twr[8 * 9 * 64 * 8];   // 147456 floats
__device__ float g_alpha[C_OUT];

// ---------------------------------------------------------------------------
// Kernel 1: ternarize (TWN) + reorganize. One block per output channel.
// ---------------------------------------------------------------------------
__global__ void ternarize_reorg_kernel(const float* __restrict__ w) {
    const int co = blockIdx.x;
    const float* wp = w + co * FILT;
    const int tid = threadIdx.x;   // 256

    __shared__ float redf[256];
    __shared__ int   redi[256];

    // pass 1: sum |w|
    float s = 0.0f;
    for (int i = tid; i < FILT; i += 256) s += fabsf(wp[i]);
    redf[tid] = s;
    __syncthreads();
    for (int st = 128; st > 0; st >>= 1) {
        if (tid < st) redf[tid] += redf[tid + st];
        __syncthreads();
    }
    const float delta = (0.7f / (float)FILT) * redf[0];
    __syncthreads();

    // pass 2: count & masked sum
    float ms = 0.0f; int cnt = 0;
    for (int i = tid; i < FILT; i += 256) {
        float a = fabsf(wp[i]);
        if (a > delta) { ms += a; cnt++; }
    }
    redf[tid] = ms; redi[tid] = cnt;
    __syncthreads();
    for (int st = 128; st > 0; st >>= 1) {
        if (tid < st) { redf[tid] += redf[tid + st]; redi[tid] += redi[tid + st]; }
        __syncthreads();
    }
    int count = redi[0];
    if (count == 0) count = 1;
    float alpha = redf[0] / (float)count;
    alpha = fmaxf(alpha, 1e-4f);
    if (tid == 0) g_alpha[co] = alpha;

    // pass 3: write ternary pattern into permuted layout
    for (int i = tid; i < FILT; i += 256) {
        float v = wp[i];
        float t = (v > delta) ? 1.0f : ((v < -delta) ? -1.0f : 0.0f);
        int ci  = i / 9;
        int khw = i - ci * 9;
        int cich = ci >> 3, cii = ci & 7;
        int slot = 2 * (cii & 3) + (cii >> 2);
        g_twr[((cich * 9 + khw) * 64 + co) * 8 + slot] = t;
    }
}

// ---------------------------------------------------------------------------
// tf32 helpers
// ---------------------------------------------------------------------------
__device__ __forceinline__ uint32_t f2tf32(float f) {
    uint32_t r;
    asm("cvt.rna.tf32.f32 %0, %1;" : "=r"(r) : "f"(f));
    return r;
}

__device__ __forceinline__ void mma_tf32(float c[4],
                                         uint32_t a0, uint32_t a1, uint32_t a2, uint32_t a3,
                                         uint32_t b0, uint32_t b1) {
    asm volatile(
        "mma.sync.aligned.m16n8k8.row.col.f32.tf32.tf32.f32 "
        "{%0,%1,%2,%3}, {%4,%5,%6,%7}, {%8,%9}, {%0,%1,%2,%3};"
        : "+f"(c[0]), "+f"(c[1]), "+f"(c[2]), "+f"(c[3])
        : "r"(a0), "r"(a1), "r"(a2), "r"(a3), "r"(b0), "r"(b1));
}

// ---------------------------------------------------------------------------
// Kernel 2: tf32 tensor-core conv.
// Grid: (2 wtiles, 224 h, 16 n). Block: 256 threads = 8 warps.
// Warp (wm 0..3, wn 0..1): 16 co x 56 w (7 n-subtiles of 8).
// K loop: 8 ci-chunks x 9 kernel shifts, k=8 per mma.
// ---------------------------------------------------------------------------
#define SX_ELEMS (3 * 114 * 8)   // 2736: [kh(3)][w(114)][slot(8)]
#define SW_ELEMS (9 * 64 * 8)    // 4608: [khw][co][slot]

__global__ __launch_bounds__(256, 2)
void conv_tc_kernel(const float* __restrict__ x,
                    const float* __restrict__ bias,
                    float* __restrict__ out) {
    __shared__ uint32_t sx[SX_ELEMS];
    __shared__ uint32_t sw[SW_ELEMS];

    const int tid  = threadIdx.x;
    const int lane = tid & 31;
    const int warp = tid >> 5;
    const int wm = warp >> 1;        // co group (0..3)
    const int wn = warp & 1;         // n group (0..1)
    const int g  = lane >> 2;        // groupID (0..7)
    const int tg = lane & 3;         // thread-in-group

    const int wt = blockIdx.x;
    const int h  = blockIdx.y;
    const int n  = blockIdx.z;
    const int w0 = wt * WTILE;

    // ---- precompute x-staging plan (chunk-invariant) ----
    int  s_sidx[11];
    int  s_goff[11];
    bool s_val[11];
#pragma unroll
    for (int j = 0; j < 11; j++) {
        int idx = tid + j * 256;
        bool act = idx < SX_ELEMS;
        int cii = idx & 7;
        int rest = idx >> 3;
        int w  = rest % 114;
        int hh = rest / 114;
        int gh = h + hh - 1;
        int gw = w0 + w - 1;
        int slot = 2 * (cii & 3) + (cii >> 2);
        s_sidx[j] = (hh * 114 + w) * 8 + slot;
        s_goff[j] = (cii * HW + gh) * HW + gw;
        s_val[j]  = act && ((unsigned)gh < (unsigned)HW) && ((unsigned)gw < (unsigned)HW);
        if (!act) s_sidx[j] = -1;
    }

    float acc[7][4];
#pragma unroll
    for (int nt = 0; nt < 7; nt++)
#pragma unroll
        for (int q = 0; q < 4; q++) acc[nt][q] = 0.0f;

    const float* xn = x + (size_t)n * C_IN * HW * HW;

    for (int cich = 0; cich < 8; cich++) {
        __syncthreads();   // previous iter done reading smem

        // ---- stage x tile (tf32-converted) ----
        const float* xb = xn + (size_t)cich * 8 * HW * HW;
#pragma unroll
        for (int j = 0; j < 11; j++) {
            if (s_sidx[j] >= 0) {
                float v = s_val[j] ? xb[s_goff[j]] : 0.0f;
                sx[s_sidx[j]] = f2tf32(v);
            }
        }
        // ---- stage weight tile (contiguous copy) ----
        {
            const uint4* wsrc = (const uint4*)(g_twr + cich * SW_ELEMS);
            uint4* wdst = (uint4*)sw;
#pragma unroll
            for (int j = 0; j < 5; j++) {
                int p = tid + j * 256;
                if (p < SW_ELEMS / 4) wdst[p] = wsrc[p];
            }
        }
        __syncthreads();

#pragma unroll
        for (int khw = 0; khw < 9; khw++) {
            const int kh = khw / 3;
            const int kw = khw - kh * 3;

            // A fragments: rows (wm*16+g, +8), cols (tg, tg+4)
            const uint32_t* ap = sw + (khw * 64 + wm * 16 + g) * 8 + 2 * tg;
            uint2 pa_lo = *(const uint2*)ap;          // a0, a2
            uint2 pa_hi = *(const uint2*)(ap + 64);   // a1, a3  (co+8 -> +8*8 elems)

#pragma unroll
            for (int nt = 0; nt < 7; nt++) {
                int ws = wn * 56 + nt * 8 + g + kw;   // input-w index within sx
                const uint32_t* bp = sx + (kh * 114 + ws) * 8 + 2 * tg;
                uint2 pb = *(const uint2*)bp;          // b0, b1
                mma_tf32(acc[nt], pa_lo.x, pa_hi.x, pa_lo.y, pa_hi.y, pb.x, pb.y);
            }
        }
    }

    // ---- epilogue: out = alpha*acc + bias ----
    const int co0 = wm * 16 + g;
    const int co1 = co0 + 8;
    const float a0 = g_alpha[co0], a1 = g_alpha[co1];
    const float b0 = bias[co0],    b1 = bias[co1];

    float* o0 = out + (((size_t)n * C_OUT + co0) * HW + h) * HW;
    float* o1 = out + (((size_t)n * C_OUT + co1) * HW + h) * HW;
#pragma unroll
    for (int nt = 0; nt < 7; nt++) {
        int wc = w0 + wn * 56 + nt * 8 + 2 * tg;
        float2 r0, r1;
        r0.x = a0 * acc[nt][0] + b0;
        r0.y = a0 * acc[nt][1] + b0;
        r1.x = a1 * acc[nt][2] + b1;
        r1.y = a1 * acc[nt][3] + b1;
        *(float2*)(o0 + wc) = r0;
        *(float2*)(o1 + wc) = r1;
    }
}

// ---------------------------------------------------------------------------
extern "C" void kernel_launch(void* const* d_in, const int* in_sizes, int n_in,
                              void* d_out, int out_size) {
    const float* x      = (const float*)d_in[0];
    const float* weight = (const float*)d_in[1];
    const float* bias   = (const float*)d_in[2];
    float* out = (float*)d_out;

    ternarize_reorg_kernel<<<C_OUT, 256>>>(weight);

    dim3 grid(HW / WTILE, HW, N_BATCH);   // (2, 224, 16)
    conv_tc_kernel<<<grid, 256>>>(x, bias, out);
}